// round 7
// baseline (speedup 1.0000x reference)
#include <cuda_runtime.h>

// HMM forward (log-space) as a scaled linear recurrence.
//   Published z_t[r] = (A p~_{t-1})[r] / max(p~_{t-1})    (NO Bv factor)
//   Consumers stage p~_t[j] = z_t[j] * Bv[t][j]  (fold Bv during staging)
//   alpha_t[r] = L_{t-1} + log(acc) + logBv[t][r],  L_t = L_{t-1} + log(m)
//
// Sync: data-as-flag. Per-step slots g_pall[t][1024] poisoned to -1; z > 0
// means published; consumers ld.volatile-spin on their own 8 B. One
// __syncthreads per step (double-buffered smem staging).
//
// 64 CTAs x 512 thr (one wave), warp-per-row, A rows in registers.

#define NZ 1024
#define NX 4096
#define KCTA 64
#define RPC 16
#define MTHREADS 512

__device__ float g_Bv[NX * NZ];     // Bv[t][i] = B[i,obs[t]]       (16 MB)
__device__ float g_logBv[NX * NZ];  // log Bv                        (16 MB)
__device__ float g_pall[NX * NZ];   // per-step published z slots    (16 MB)
__device__ float g_rinvA[NZ];
__device__ float g_rinvB[NZ];

// ---------------------------------------------------------------------------
__global__ void k_rowsums(const float* __restrict__ trans,
                          const float* __restrict__ emis) {
    int i = blockIdx.x, tid = threadIdx.x, lane = tid & 31, w = tid >> 5;
    __shared__ float smA[8], smB[8];
    float sA = 0.f, sB = 0.f;
#pragma unroll
    for (int k = 0; k < 4; k++)  sA += trans[i * NZ + tid + 256 * k];
#pragma unroll
    for (int k = 0; k < 16; k++) sB += emis[i * NX + tid + 256 * k];
#pragma unroll
    for (int o = 16; o > 0; o >>= 1) {
        sA += __shfl_xor_sync(0xffffffffu, sA, o);
        sB += __shfl_xor_sync(0xffffffffu, sB, o);
    }
    if (lane == 0) { smA[w] = sA; smB[w] = sB; }
    __syncthreads();
    if (tid == 0) {
        float a = 0.f, b = 0.f;
#pragma unroll
        for (int j = 0; j < 8; j++) { a += smA[j]; b += smB[j]; }
        g_rinvA[i] = 1.0f / a;
        g_rinvB[i] = 1.0f / b;
    }
}

// ---------------------------------------------------------------------------
__global__ void k_bv(const int* __restrict__ obs,
                     const float* __restrict__ emis) {
    int t = blockIdx.x;
    int o = __ldg(&obs[t]);
#pragma unroll
    for (int k = 0; k < 4; k++) {
        int i = threadIdx.x + 256 * k;
        float v = emis[i * NX + o] * g_rinvB[i];
        g_Bv[t * NZ + i]    = v;
        g_logBv[t * NZ + i] = logf(v);
    }
}

// ---------------------------------------------------------------------------
__global__ void k_poison() {
    int idx = (blockIdx.x * 256 + threadIdx.x) * 4;
    *(float4*)&g_pall[idx] = make_float4(-1.f, -1.f, -1.f, -1.f);
}

// ---------------------------------------------------------------------------
// k_init: publish z_0 = pi/sum (WITHOUT Bv; consumers fold Bv_0 at staging).
// alpha_0 = log(z_0) + logBv_0.
// ---------------------------------------------------------------------------
__global__ void k_init(const float* __restrict__ sp,
                       float* __restrict__ alpha) {
    int tid = threadIdx.x, lane = tid & 31, w = tid >> 5;
    __shared__ float sm[32];
    __shared__ float bc_invS;

    float v = sp[tid];
    float s = v;
#pragma unroll
    for (int o = 16; o > 0; o >>= 1) s += __shfl_xor_sync(0xffffffffu, s, o);
    if (lane == 0) sm[w] = s;
    __syncthreads();
    if (tid == 0) {
        float a = 0.f;
#pragma unroll
        for (int j = 0; j < 32; j++) a += sm[j];
        bc_invS = 1.0f / a;
    }
    __syncthreads();

    float z0 = v * bc_invS;                        // pi normalized, no Bv
    alpha[tid * NX] = logf(z0 * g_Bv[tid]);        // alpha_0 (L0 = 0)
    __stcg(&g_pall[tid], z0);                      // publish slot 0
}

// ---------------------------------------------------------------------------
// Persistent main loop. Warp w of CTA b owns row r = b*16 + w.
// Lane l holds A[r][4l + 128k + c] in registers.
// ---------------------------------------------------------------------------
__global__ void __launch_bounds__(MTHREADS, 1)
k_main(const float* __restrict__ trans, float* __restrict__ alpha) {
    __shared__ float ps[2][NZ];
    int tid = threadIdx.x, lane = tid & 31, w = tid >> 5;
    int r = blockIdx.x * RPC + w;

    float rinv = g_rinvA[r];
    float4 A[8];
#pragma unroll
    for (int k = 0; k < 8; k++) {
        float4 a = *(const float4*)&trans[r * NZ + 4 * lane + 128 * k];
        a.x *= rinv; a.y *= rinv; a.z *= rinv; a.w *= rinv;
        A[k] = a;
    }

    float L = 0.f;
    float aacc = 0.f;                               // alpha chunk buffer
    // Prefetch for t=1: staging Bv_{0} (per-thread float2) and logBv_1 (bcast)
    float2 bvs = *(const float2*)&g_Bv[2 * tid];            // Bv[0][2tid..]
    float  lbv = __ldg(&g_logBv[NZ + r]);                   // logBv[1][r]

    for (int t = 1; t < NX; t++) {
        const float* src = &g_pall[(t - 1) * NZ];
        float*       dst = &g_pall[t * NZ];
        float*       buf = ps[t & 1];

        // ---- spin on own 8 B of step-(t-1) data; fold Bv while staging ----
        float x0, x1;
        const float* a0p = src + 2 * tid;
        do {
            asm volatile("ld.volatile.global.v2.f32 {%0,%1}, [%2];"
                         : "=f"(x0), "=f"(x1) : "l"(a0p) : "memory");
        } while (x0 < 0.f || x1 < 0.f);
        buf[2 * tid]     = x0 * bvs.x;
        buf[2 * tid + 1] = x1 * bvs.y;
        __syncthreads();                            // ONLY barrier this step

        // ---- dot (A regs x p~ smem), max folded into the same pass ----
        float s0 = 0.f, s1 = 0.f, s2 = 0.f, s3 = 0.f;
        float m0 = 0.f, m1 = 0.f, m2 = 0.f, m3 = 0.f;
#pragma unroll
        for (int k = 0; k < 8; k++) {
            float4 p = *(const float4*)&buf[4 * lane + 128 * k];
            s0 = fmaf(A[k].x, p.x, s0);  m0 = fmaxf(m0, p.x);
            s1 = fmaf(A[k].y, p.y, s1);  m1 = fmaxf(m1, p.y);
            s2 = fmaf(A[k].z, p.z, s2);  m2 = fmaxf(m2, p.z);
            s3 = fmaf(A[k].w, p.w, s3);  m3 = fmaxf(m3, p.w);
        }
        float acc = (s0 + s1) + (s2 + s3);
        float m   = fmaxf(fmaxf(m0, m1), fmaxf(m2, m3));
#pragma unroll
        for (int o = 16; o > 0; o >>= 1) {          // interleaved dual ladder
            acc += __shfl_xor_sync(0xffffffffu, acc, o);
            m    = fmaxf(m, __shfl_xor_sync(0xffffffffu, m, o));
        }

        // ---- publish ASAP: z_t[r] = acc / m  (no Bv on this path) ----
        if (lane == 0)
            __stcg(&dst[r], __fdividef(acc, m));

        // ---- off critical path: alpha (all lanes), L, prefetches ----
        float aval = L + __logf(acc) + lbv;         // every lane has acc & lbv
        L += __logf(m);
        if (lane == (t & 31)) aacc = aval;
        if ((t & 31) == 31) {
            int tbase = t & ~31;
            if (tbase + lane >= 1)                  // t=0 written by k_init
                alpha[r * NX + tbase + lane] = aacc;
        }
        if (t + 1 < NX) {
            bvs = *(const float2*)&g_Bv[t * NZ + 2 * tid];      // Bv[t] for t+1 staging
            lbv = __ldg(&g_logBv[(t + 1) * NZ + r]);            // logBv[t+1][r]
        }
    }
}

// ---------------------------------------------------------------------------
extern "C" void kernel_launch(void* const* d_in, const int* in_sizes, int n_in,
                              void* d_out, int out_size) {
    const int*   obs   = (const int*)d_in[0];
    const float* sp    = (const float*)d_in[1];
    const float* trans = (const float*)d_in[2];
    const float* emis  = (const float*)d_in[3];
    float*       alpha = (float*)d_out;

    k_rowsums<<<NZ, 256>>>(trans, emis);
    k_bv<<<NX, 256>>>(obs, emis);
    k_poison<<<(NX * NZ) / (256 * 4), 256>>>();
    k_init<<<1, 1024>>>(sp, alpha);
    k_main<<<KCTA, MTHREADS>>>(trans, alpha);
}

// round 8
// speedup vs baseline: 1.7711x; 1.7711x over previous
#include <cuda_runtime.h>

// HMM forward (log-space) as a scaled linear recurrence.
//   Staged (smem) w_t = y_{t-1} * Bv[t-1] / M_{t-1}   (consumers fold factor)
//   Published y_t[r] = acc_t[r] = sum_j A[r][j] * w_t[j]    (RAW dot, no div/bv)
//   alpha_t[r] = L + log(acc_t[r]) + logBv[t][r];  L += log(M_t), M_t = max(w_t)
// Every CTA computes the same M_t during its own dot pass -> the next staging
// factor f = Bv[t]*(1/M_t) is built in the epilogue, OFF the critical path.
//
// Sync: data-as-flag (slots poisoned to -1, acc>0 == published), per-thread
// 8B volatile polls. TWO __syncthreads per step: tail barrier keeps fast
// warps' poll LDGs from interleaving with slow warps' dot LDS (round-7 lesson).
//
// 64 CTAs x 512 thr (one wave), warp-per-row, A rows in registers.

#define NZ 1024
#define NX 4096
#define KCTA 64
#define RPC 16
#define MTHREADS 512

__device__ float g_Bv[NX * NZ];     // Bv[t][i] = B[i,obs[t]]       (16 MB)
__device__ float g_logBv[NX * NZ];  // log Bv                        (16 MB)
__device__ float g_pall[NX * NZ];   // per-step published y slots    (16 MB)
__device__ float g_rinvA[NZ];
__device__ float g_rinvB[NZ];

// ---------------------------------------------------------------------------
__global__ void k_rowsums(const float* __restrict__ trans,
                          const float* __restrict__ emis) {
    int i = blockIdx.x, tid = threadIdx.x, lane = tid & 31, w = tid >> 5;
    __shared__ float smA[8], smB[8];
    float sA = 0.f, sB = 0.f;
#pragma unroll
    for (int k = 0; k < 4; k++)  sA += trans[i * NZ + tid + 256 * k];
#pragma unroll
    for (int k = 0; k < 16; k++) sB += emis[i * NX + tid + 256 * k];
#pragma unroll
    for (int o = 16; o > 0; o >>= 1) {
        sA += __shfl_xor_sync(0xffffffffu, sA, o);
        sB += __shfl_xor_sync(0xffffffffu, sB, o);
    }
    if (lane == 0) { smA[w] = sA; smB[w] = sB; }
    __syncthreads();
    if (tid == 0) {
        float a = 0.f, b = 0.f;
#pragma unroll
        for (int j = 0; j < 8; j++) { a += smA[j]; b += smB[j]; }
        g_rinvA[i] = 1.0f / a;
        g_rinvB[i] = 1.0f / b;
    }
}

// ---------------------------------------------------------------------------
__global__ void k_bv(const int* __restrict__ obs,
                     const float* __restrict__ emis) {
    int t = blockIdx.x;
    int o = __ldg(&obs[t]);
#pragma unroll
    for (int k = 0; k < 4; k++) {
        int i = threadIdx.x + 256 * k;
        float v = emis[i * NX + o] * g_rinvB[i];
        g_Bv[t * NZ + i]    = v;
        g_logBv[t * NZ + i] = logf(v);
    }
}

// ---------------------------------------------------------------------------
__global__ void k_poison() {
    int idx = (blockIdx.x * 256 + threadIdx.x) * 4;
    *(float4*)&g_pall[idx] = make_float4(-1.f, -1.f, -1.f, -1.f);
}

// ---------------------------------------------------------------------------
// k_init: publish y_0 = pi (normalized start_prob, WITHOUT Bv — consumers
// fold Bv[0] at staging with M_0 = 1). alpha_0 = log(pi * Bv[0]).
// ---------------------------------------------------------------------------
__global__ void k_init(const float* __restrict__ sp,
                       float* __restrict__ alpha) {
    int tid = threadIdx.x, lane = tid & 31, w = tid >> 5;
    __shared__ float sm[32];
    __shared__ float bc_invS;

    float v = sp[tid];
    float s = v;
#pragma unroll
    for (int o = 16; o > 0; o >>= 1) s += __shfl_xor_sync(0xffffffffu, s, o);
    if (lane == 0) sm[w] = s;
    __syncthreads();
    if (tid == 0) {
        float a = 0.f;
#pragma unroll
        for (int j = 0; j < 32; j++) a += sm[j];
        bc_invS = 1.0f / a;
    }
    __syncthreads();

    float pi = v * bc_invS;
    alpha[tid * NX] = logf(pi * g_Bv[tid]);   // alpha_0 (L0 = 0)
    __stcg(&g_pall[tid], pi);                 // publish y_0 (no Bv)
}

// ---------------------------------------------------------------------------
// Persistent main loop. Warp w of CTA b owns row r = b*16 + w.
// Lane l holds A[r][4l + 128k + c] in registers.
// ---------------------------------------------------------------------------
__global__ void __launch_bounds__(MTHREADS, 1)
k_main(const float* __restrict__ trans, float* __restrict__ alpha) {
    __shared__ float ps[NZ];
    int tid = threadIdx.x, lane = tid & 31, w = tid >> 5;
    int r = blockIdx.x * RPC + w;

    float rinv = g_rinvA[r];
    float4 A[8];
#pragma unroll
    for (int k = 0; k < 8; k++) {
        float4 a = *(const float4*)&trans[r * NZ + 4 * lane + 128 * k];
        a.x *= rinv; a.y *= rinv; a.z *= rinv; a.w *= rinv;
        A[k] = a;
    }

    float L = 0.f;
    float aacc = 0.f;                          // alpha chunk buffer (lane t&31)

    // Staging-factor pipeline (depth 2 on the Bv row loads):
    //   f   = Bv[t-1]*(1/M)  -> used at staging of step t   (M_0 = 1)
    //   bvA = Bv[t]  row      (consumed in epilogue of step t -> f for t+1)
    //   bvB = Bv[t+1] row     (in flight, >=1 full step of slack)
    float2 f   = *(const float2*)&g_Bv[2 * tid];              // Bv[0] * 1
    float2 bvA = *(const float2*)&g_Bv[NZ + 2 * tid];         // Bv[1]
    float2 bvB = *(const float2*)&g_Bv[2 * NZ + 2 * tid];     // Bv[2]
    float  lbv = __ldg(&g_logBv[NZ + r]);                     // logBv[1][r]

    for (int t = 1; t < NX; t++) {
        const float* src = &g_pall[(t - 1) * NZ];
        float*       dst = &g_pall[t * NZ];

        // ---- spin on own 8 B of step-(t-1) data; fold factor at staging ----
        float x0, x1;
        const float* a0p = src + 2 * tid;
        do {
            asm volatile("ld.volatile.global.v2.f32 {%0,%1}, [%2];"
                         : "=f"(x0), "=f"(x1) : "l"(a0p) : "memory");
        } while (fminf(x0, x1) < 0.f);
        ps[2 * tid]     = x0 * f.x;
        ps[2 * tid + 1] = x1 * f.y;
        __syncthreads();

        // ---- dot (A regs x w smem), max of w folded into the same pass ----
        float s0 = 0.f, s1 = 0.f, s2 = 0.f, s3 = 0.f;
        float m0 = 0.f, m1 = 0.f, m2 = 0.f, m3 = 0.f;
#pragma unroll
        for (int k = 0; k < 8; k++) {
            float4 p = *(const float4*)&ps[4 * lane + 128 * k];
            s0 = fmaf(A[k].x, p.x, s0);  m0 = fmaxf(m0, p.x);
            s1 = fmaf(A[k].y, p.y, s1);  m1 = fmaxf(m1, p.y);
            s2 = fmaf(A[k].z, p.z, s2);  m2 = fmaxf(m2, p.z);
            s3 = fmaf(A[k].w, p.w, s3);  m3 = fmaxf(m3, p.w);
        }
        float acc = (s0 + s1) + (s2 + s3);
        float m   = fmaxf(fmaxf(m0, m1), fmaxf(m2, m3));
#pragma unroll
        for (int o = 16; o > 0; o >>= 1) {     // interleaved dual ladder
            acc += __shfl_xor_sync(0xffffffffu, acc, o);
            m    = fmaxf(m, __shfl_xor_sync(0xffffffffu, m, o));
        }

        // ---- publish IMMEDIATELY: raw acc (no divide, no bv multiply) ----
        if (lane == 0)
            __stcg(&dst[r], acc);

        // ---- off critical path: alpha, L, next staging factor, prefetch ----
        float aval = L + __logf(acc) + lbv;    // every lane holds acc & lbv
        float rm = __fdividef(1.0f, m);
        L += __logf(m);
        f.x = bvA.x * rm;                      // factor for staging at t+1
        f.y = bvA.y * rm;
        bvA = bvB;                             // shift Bv pipeline
        if (lane == (t & 31)) aacc = aval;
        if ((t & 31) == 31) {
            int tbase = t & ~31;
            if (tbase + lane >= 1)             // t=0 written by k_init
                alpha[r * NX + tbase + lane] = aacc;
        }
        if (t + 2 < NX)
            bvB = *(const float2*)&g_Bv[(t + 2) * NZ + 2 * tid];
        if (t + 1 < NX)
            lbv = __ldg(&g_logBv[(t + 1) * NZ + r]);

        __syncthreads();   // isolate polls from dots (round-7 lesson) + ps reuse
    }
}

// ---------------------------------------------------------------------------
extern "C" void kernel_launch(void* const* d_in, const int* in_sizes, int n_in,
                              void* d_out, int out_size) {
    const int*   obs   = (const int*)d_in[0];
    const float* sp    = (const float*)d_in[1];
    const float* trans = (const float*)d_in[2];
    const float* emis  = (const float*)d_in[3];
    float*       alpha = (float*)d_out;

    k_rowsums<<<NZ, 256>>>(trans, emis);
    k_bv<<<NX, 256>>>(obs, emis);
    k_poison<<<(NX * NZ) / (256 * 4), 256>>>();
    k_init<<<1, 1024>>>(sp, alpha);
    k_main<<<KCTA, MTHREADS>>>(trans, alpha);
}